// round 7
// baseline (speedup 1.0000x reference)
#include <cuda_runtime.h>
#include <cuda_bf16.h>
#include <math.h>
#include <stdint.h>

#define N_TOK  32768
#define DDIM   256
#define KCODE  1024
#define HW_    1024
#define BATCH  32
#define MARGIN 2.0e-3f
#define CAND_CAP 32

// ---- scratch (static device globals; no allocations allowed) ----
__device__ float  g_eNorm[KCODE];
__device__ float  g_znorm[N_TOK];
__device__ float  g_sumE[DDIM];
__device__ float  g_sumZ[DDIM];
__device__ int    g_counts[KCODE];
__device__ int    g_idx[N_TOK];
__device__ double g_loss_acc;
__device__ double g_zsq_acc;
__device__ double g_e2_acc;

__device__ __nv_bfloat16 g_Zb[(size_t)N_TOK * DDIM];    // 16MB token-major bf16
__device__ float         g_Zt[(size_t)N_TOK * DDIM];    // 32MB token-major fp32
__device__ __nv_bfloat16 g_Eb[(size_t)KCODE * DDIM];    // 512KB

// ------------------------------------------------------------------
__global__ void k_zero() {
    int t = blockIdx.x * 256 + threadIdx.x;
    if (t < KCODE) g_counts[t] = 0;
    if (t < DDIM)  g_sumE[t] = 0.f;
    if (t == 0) { g_loss_acc = 0.0; g_zsq_acc = 0.0; g_e2_acc = 0.0; }
}

// one pass over E: per-code norm, bf16 convert, column sums, total e^2
__global__ void k_estats(const float* __restrict__ E) {
    int k = blockIdx.x;
    int t = threadIdx.x;                      // 64 threads, 4 floats each
    float4 v = ((const float4*)(E + (size_t)k * DDIM))[t];

    // bf16 convert (8B per thread)
    union { uint2 u; __nv_bfloat162 h2[2]; } pk;
    pk.h2[0] = __floats2bfloat162_rn(v.x, v.y);
    pk.h2[1] = __floats2bfloat162_rn(v.z, v.w);
    *(uint2*)&g_Eb[(size_t)k * DDIM + t * 4] = pk.u;

    // column sums
    atomicAdd(&g_sumE[t * 4 + 0], v.x);
    atomicAdd(&g_sumE[t * 4 + 1], v.y);
    atomicAdd(&g_sumE[t * 4 + 2], v.z);
    atomicAdd(&g_sumE[t * 4 + 3], v.w);

    // squared norm
    float s = v.x * v.x + v.y * v.y + v.z * v.z + v.w * v.w;
    #pragma unroll
    for (int o = 16; o; o >>= 1) s += __shfl_down_sync(0xffffffffu, s, o);
    __shared__ float ws[2];
    if ((t & 31) == 0) ws[t >> 5] = s;
    __syncthreads();
    if (t == 0) {
        float tot = ws[0] + ws[1];
        g_eNorm[k] = tot;
        atomicAdd(&g_e2_acc, (double)tot);
    }
}

// per-d sums of Z and total sum of z^2 (for mean_distance)
__global__ void k_sumz(const float* __restrict__ Z) {
    int d = blockIdx.x;
    int tid = threadIdx.x;
    float  s = 0.f;
    double q = 0.0;
    for (int b = 0; b < BATCH; b++) {
        const float* p = Z + ((size_t)b * DDIM + d) * HW_;
        #pragma unroll
        for (int base = 0; base < HW_; base += 256) {
            float v = p[base + tid];
            s += v;
            q += (double)v * (double)v;
        }
    }
    __shared__ float  sf[256];
    __shared__ double sd[256];
    sf[tid] = s; sd[tid] = q;
    __syncthreads();
    for (int o = 128; o; o >>= 1) {
        if (tid < o) { sf[tid] += sf[tid + o]; sd[tid] += sd[tid + o]; }
        __syncthreads();
    }
    if (tid == 0) {
        g_sumZ[d] = sf[0];
        atomicAdd(&g_zsq_acc, sd[0]);
    }
}

// ------------------------------------------------------------------
// transpose Z [b,d,hw] -> token-major Zt (fp32) + Zb (bf16) + per-token znorm
__global__ __launch_bounds__(256) void k_prep(const float* __restrict__ Z) {
    __shared__ float tile[256][33];
    __shared__ float znpart[8][32];
    int tid = threadIdx.x;
    int b   = blockIdx.x >> 5;
    int hw0 = (blockIdx.x & 31) << 5;
    int lane = tid & 31, dg = tid >> 5;     // dg 0..7
    #pragma unroll
    for (int i = 0; i < 32; i++) {
        int d = dg * 32 + i;
        tile[d][lane] = Z[(((size_t)b * DDIM + d) << 10) + hw0 + lane];
    }
    __syncthreads();
    int h = tid & 31, ds = tid >> 5;        // ds 0..7 (d segment of 32)
    size_t tk = (size_t)b * 1024 + hw0 + h;
    float buf[32];
    float zp = 0.f;
    #pragma unroll
    for (int i = 0; i < 32; i++) {
        buf[i] = tile[ds * 32 + i][h];
        zp += buf[i] * buf[i];
    }
    znpart[ds][h] = zp;
    #pragma unroll
    for (int q = 0; q < 8; q++)
        *(float4*)&g_Zt[tk * DDIM + ds * 32 + q * 4] =
            make_float4(buf[q*4], buf[q*4+1], buf[q*4+2], buf[q*4+3]);
    #pragma unroll
    for (int q = 0; q < 4; q++) {
        union { uint4 u; __nv_bfloat162 h2[4]; } pk;
        #pragma unroll
        for (int j = 0; j < 4; j++)
            pk.h2[j] = __floats2bfloat162_rn(buf[q*8 + j*2], buf[q*8 + j*2 + 1]);
        *(uint4*)&g_Zb[tk * DDIM + ds * 32 + q * 8] = pk.u;
    }
    __syncthreads();
    if (tid < 32) {
        float s = znpart[0][tid];
        #pragma unroll
        for (int dd = 1; dd < 8; dd++) s += znpart[dd][tid];
        g_znorm[(size_t)b * 1024 + hw0 + tid] = s;
    }
}

// ------------------------------------------------------------------
__device__ __forceinline__ void mma_bf16(float* c, const uint32_t* a, const uint32_t* b) {
    asm volatile(
        "mma.sync.aligned.m16n8k16.row.col.f32.bf16.bf16.f32 "
        "{%0,%1,%2,%3}, {%4,%5,%6,%7}, {%8,%9}, {%0,%1,%2,%3};\n"
        : "+f"(c[0]), "+f"(c[1]), "+f"(c[2]), "+f"(c[3])
        : "r"(a[0]), "r"(a[1]), "r"(a[2]), "r"(a[3]), "r"(b[0]), "r"(b[1]));
}

// Fused bf16-MMA argmin: CTA = 256 tokens x full K (16 chunks of 64 codes).
// Per-chunk epilogue keeps a running per-token min + margin candidates in smem;
// final phase rescores candidates exactly in fp32 with the reference's
// rounding structure and lowest-index tie-break.
// smem u32 layout: As 33792 | Bs 8448 | runmin 256 | chmin 512 | cnt 256 | cand 4096
#define SM_AS   0
#define SM_BS   33792
#define SM_RMIN (33792 + 8448)
#define SM_CMIN (SM_RMIN + 256)
#define SM_CNT  (SM_CMIN + 512)
#define SM_CAND (SM_CNT + 256)
#define SMEM_MMA_BYTES ((SM_CAND + 4096) * 4)

__global__ __launch_bounds__(512) void k_mma(const float* __restrict__ E) {
    extern __shared__ uint32_t sm[];
    uint32_t* As = sm + SM_AS;           // [256][132]
    uint32_t* Bs = sm + SM_BS;           // [64][132]
    float*  runmin = (float*)(sm + SM_RMIN);
    float*  chmin  = (float*)(sm + SM_CMIN);   // [256][2]
    int*    cnt    = (int*)(sm + SM_CNT);
    unsigned short* cand = (unsigned short*)(sm + SM_CAND); // [256][32]

    int tid = threadIdx.x;
    int tb  = blockIdx.x;                // 0..127, 256 tokens each

    if (tid < 256) { runmin[tid] = 3.4e38f; cnt[tid] = 0; }

    // load A tile (256 tokens x 256 d bf16)
    #pragma unroll
    for (int i = 0; i < 16; i++) {
        int c = tid + 512 * i;
        int row = c >> 5, col = c & 31;
        uint4 v = *(const uint4*)(g_Zb + ((size_t)(tb * 256 + row)) * DDIM + col * 8);
        *(uint4*)(As + row * 132 + col * 4) = v;
    }

    int w = tid >> 5, l = tid & 31;
    int m0 = (w & 7) * 32, n0 = (w >> 3) * 32;
    int ng = w >> 3;
    int l4 = l >> 2, lm = l & 3;

    float acc[2][4][4];
    #pragma unroll
    for (int mf = 0; mf < 2; mf++)
        #pragma unroll
        for (int nf = 0; nf < 4; nf++)
            #pragma unroll
            for (int q = 0; q < 4; q++) acc[mf][nf][q] = 0.f;

    for (int ch = 0; ch < 16; ch++) {
        __syncthreads();
        #pragma unroll
        for (int i = 0; i < 4; i++) {
            int c = tid + 512 * i;
            int row = c >> 5, col = c & 31;
            uint4 v = *(const uint4*)(g_Eb + ((size_t)(ch * 64 + row)) * DDIM + col * 8);
            *(uint4*)(Bs + row * 132 + col * 4) = v;
        }
        __syncthreads();

        #pragma unroll
        for (int ks = 0; ks < 16; ks++) {
            int ka = ks * 8 + lm;
            uint32_t a[2][4], b[4][2];
            #pragma unroll
            for (int mf = 0; mf < 2; mf++) {
                int r = m0 + mf * 16 + l4;
                a[mf][0] = As[r * 132 + ka];
                a[mf][1] = As[(r + 8) * 132 + ka];
                a[mf][2] = As[r * 132 + ka + 4];
                a[mf][3] = As[(r + 8) * 132 + ka + 4];
            }
            #pragma unroll
            for (int nf = 0; nf < 4; nf++) {
                int n = n0 + nf * 8 + l4;
                b[nf][0] = Bs[n * 132 + ka];
                b[nf][1] = Bs[n * 132 + ka + 4];
            }
            #pragma unroll
            for (int mf = 0; mf < 2; mf++)
                #pragma unroll
                for (int nf = 0; nf < 4; nf++)
                    mma_bf16(acc[mf][nf], a[mf], b[nf]);
        }

        // --- epilogue: s = en - 2*dot (in place), chunk-min, candidates ---
        float rmin[2][2];
        #pragma unroll
        for (int mf = 0; mf < 2; mf++) {
            rmin[mf][0] = 3.4e38f; rmin[mf][1] = 3.4e38f;
            #pragma unroll
            for (int nf = 0; nf < 4; nf++) {
                int cg = ch * 64 + n0 + nf * 8 + lm * 2;
                float2 en = *(const float2*)&g_eNorm[cg];
                acc[mf][nf][0] = en.x - 2.f * acc[mf][nf][0];
                acc[mf][nf][1] = en.y - 2.f * acc[mf][nf][1];
                acc[mf][nf][2] = en.x - 2.f * acc[mf][nf][2];
                acc[mf][nf][3] = en.y - 2.f * acc[mf][nf][3];
                rmin[mf][0] = fminf(rmin[mf][0], fminf(acc[mf][nf][0], acc[mf][nf][1]));
                rmin[mf][1] = fminf(rmin[mf][1], fminf(acc[mf][nf][2], acc[mf][nf][3]));
            }
        }
        #pragma unroll
        for (int mf = 0; mf < 2; mf++)
            #pragma unroll
            for (int hf = 0; hf < 2; hf++) {
                float v = rmin[mf][hf];
                v = fminf(v, __shfl_xor_sync(0xffffffffu, v, 1));
                v = fminf(v, __shfl_xor_sync(0xffffffffu, v, 2));
                rmin[mf][hf] = v;
            }
        if (lm == 0) {
            #pragma unroll
            for (int mf = 0; mf < 2; mf++)
                #pragma unroll
                for (int hf = 0; hf < 2; hf++)
                    chmin[(m0 + mf * 16 + hf * 8 + l4) * 2 + ng] = rmin[mf][hf];
        }
        __syncthreads();
        if (tid < 256)
            runmin[tid] = fminf(runmin[tid], fminf(chmin[tid * 2], chmin[tid * 2 + 1]));
        __syncthreads();

        #pragma unroll
        for (int mf = 0; mf < 2; mf++) {
            int r0 = m0 + mf * 16 + l4;
            float t0 = runmin[r0] + MARGIN;
            float t1 = runmin[r0 + 8] + MARGIN;
            #pragma unroll
            for (int nf = 0; nf < 4; nf++) {
                int cg = ch * 64 + n0 + nf * 8 + lm * 2;
                if (acc[mf][nf][0] <= t0) {
                    int p = atomicAdd(&cnt[r0], 1);
                    if (p < CAND_CAP) cand[r0 * CAND_CAP + p] = (unsigned short)cg;
                }
                if (acc[mf][nf][1] <= t0) {
                    int p = atomicAdd(&cnt[r0], 1);
                    if (p < CAND_CAP) cand[r0 * CAND_CAP + p] = (unsigned short)(cg + 1);
                }
                if (acc[mf][nf][2] <= t1) {
                    int p = atomicAdd(&cnt[r0 + 8], 1);
                    if (p < CAND_CAP) cand[(r0 + 8) * CAND_CAP + p] = (unsigned short)cg;
                }
                if (acc[mf][nf][3] <= t1) {
                    int p = atomicAdd(&cnt[r0 + 8], 1);
                    if (p < CAND_CAP) cand[(r0 + 8) * CAND_CAP + p] = (unsigned short)(cg + 1);
                }
                acc[mf][nf][0] = 0.f; acc[mf][nf][1] = 0.f;
                acc[mf][nf][2] = 0.f; acc[mf][nf][3] = 0.f;
            }
        }
    }
    __syncthreads();

    // --- exact fp32 rescore of candidates (warp per 16 tokens) ---
    for (int i = 0; i < 16; i++) {
        int tl = w * 16 + i;
        int t  = tb * 256 + tl;
        float zr[8];
        *(float4*)&zr[0] = *(const float4*)&g_Zt[(size_t)t * DDIM + l * 8];
        *(float4*)&zr[4] = *(const float4*)&g_Zt[(size_t)t * DDIM + l * 8 + 4];
        float szn = g_znorm[t];
        int c = cnt[tl];
        float best = 3.4e38f;
        int   bidx = 0;
        if (c <= CAND_CAP) {
            for (int j = 0; j < c; j++) {
                int code = cand[tl * CAND_CAP + j];
                const float* e = E + (size_t)code * DDIM + l * 8;
                float4 e0 = *(const float4*)e;
                float4 e1 = *(const float4*)(e + 4);
                float p = zr[0] * e0.x;
                p = fmaf(zr[1], e0.y, p);
                p = fmaf(zr[2], e0.z, p);
                p = fmaf(zr[3], e0.w, p);
                p = fmaf(zr[4], e1.x, p);
                p = fmaf(zr[5], e1.y, p);
                p = fmaf(zr[6], e1.z, p);
                p = fmaf(zr[7], e1.w, p);
                #pragma unroll
                for (int o = 16; o; o >>= 1) p += __shfl_xor_sync(0xffffffffu, p, o);
                float t1 = __fadd_rn(szn, g_eNorm[code]);
                float s  = __fadd_rn(t1, -2.0f * p);
                if (s < best || (s == best && code < bidx)) { best = s; bidx = code; }
            }
        } else {
            // overflow fallback: exact scan of all codes (never expected)
            for (int code = 0; code < KCODE; code++) {
                const float* e = E + (size_t)code * DDIM + l * 8;
                float4 e0 = *(const float4*)e;
                float4 e1 = *(const float4*)(e + 4);
                float p = zr[0] * e0.x;
                p = fmaf(zr[1], e0.y, p);
                p = fmaf(zr[2], e0.z, p);
                p = fmaf(zr[3], e0.w, p);
                p = fmaf(zr[4], e1.x, p);
                p = fmaf(zr[5], e1.y, p);
                p = fmaf(zr[6], e1.z, p);
                p = fmaf(zr[7], e1.w, p);
                #pragma unroll
                for (int o = 16; o; o >>= 1) p += __shfl_xor_sync(0xffffffffu, p, o);
                float t1 = __fadd_rn(szn, g_eNorm[code]);
                float s  = __fadd_rn(t1, -2.0f * p);
                if (s < best) { best = s; bidx = code; }
            }
        }
        if (l == 0) {
            g_idx[t] = bidx;
            atomicAdd(&g_counts[bidx], 1);
        }
    }
}

// ------------------------------------------------------------------
// gather codes -> out (NCHW), accumulate loss sum
__global__ __launch_bounds__(256) void k_out(const float* __restrict__ Z,
                                             const float* __restrict__ E,
                                             float* __restrict__ out) {
    __shared__ int sidx[128];
    int tid = threadIdx.x;
    int tb  = blockIdx.x;
    int b   = tb >> 3;
    int hw0 = (tb & 7) << 7;
    if (tid < 128) sidx[tid] = g_idx[tb * 128 + tid];
    __syncthreads();

    int t  = tid & 127;
    int dg = tid >> 7;
    int myidx = sidx[t];
    size_t zb = ((size_t)b * DDIM) * HW_ + hw0 + t;

    double lsum = 0.0;
    for (int d = dg; d < DDIM; d += 2) {
        float ov = E[(size_t)myidx * DDIM + d];
        float zv = Z[zb + (size_t)d * HW_];
        out[zb + (size_t)d * HW_] = ov;
        float df = ov - zv;
        lsum += (double)df * (double)df;
    }

    __shared__ double sred[256];
    sred[tid] = lsum;
    __syncthreads();
    for (int o = 128; o; o >>= 1) {
        if (tid < o) sred[tid] += sred[tid + o];
        __syncthreads();
    }
    if (tid == 0) atomicAdd(&g_loss_acc, sred[0]);
}

// ------------------------------------------------------------------
__global__ void k_final(float* __restrict__ tail) {
    __shared__ double shd[256];
    __shared__ double she[256];
    int tid = threadIdx.x;

    double dot = (tid < DDIM) ? (double)g_sumZ[tid] * (double)g_sumE[tid] : 0.0;
    double ent = 0.0;
    for (int k = tid; k < KCODE; k += 256) {
        double p = (double)g_counts[k] / (double)N_TOK;
        ent += p * log(p + 1e-10);
    }
    shd[tid] = dot; she[tid] = ent;
    __syncthreads();
    for (int o = 128; o; o >>= 1) {
        if (tid < o) { shd[tid] += shd[tid + o]; she[tid] += she[tid + o]; }
        __syncthreads();
    }
    if (tid == 0) {
        double md = g_zsq_acc / (double)N_TOK
                  + g_e2_acc  / (double)KCODE
                  - 2.0 * shd[0] / ((double)N_TOK * (double)KCODE);
        double loss = 1.25 * g_loss_acc / ((double)N_TOK * (double)DDIM);
        double perp = exp(-she[0]);
        tail[0] = (float)loss;
        tail[1] = (float)perp;
        tail[2] = (float)md;
    }
}

// ------------------------------------------------------------------
extern "C" void kernel_launch(void* const* d_in, const int* in_sizes, int n_in,
                              void* d_out, int out_size) {
    const float* Z = (const float*)d_in[0];   // [32,256,32,32]
    const float* E = (const float*)d_in[1];   // [1024,256]
    float* out = (float*)d_out;

    cudaFuncSetAttribute(k_mma, cudaFuncAttributeMaxDynamicSharedMemorySize,
                         SMEM_MMA_BYTES);

    k_zero  <<<4, 256>>>();
    k_estats<<<KCODE, 64>>>(E);
    k_prep  <<<1024, 256>>>(Z);
    k_sumz  <<<DDIM, 256>>>(Z);
    k_mma   <<<128, 512, SMEM_MMA_BYTES>>>(E);
    k_out   <<<256, 256>>>(Z, E, out);
    k_final <<<1, 256>>>(out + (out_size - 3));
}

// round 8
// speedup vs baseline: 1.8263x; 1.8263x over previous
#include <cuda_runtime.h>
#include <cuda_bf16.h>
#include <math.h>
#include <stdint.h>

#define N_TOK  32768
#define DDIM   256
#define KCODE  1024
#define HW_    1024
#define BATCH  32
#define MARGIN 2.0e-3f
#define CAND_CAP 32

// ---- scratch (static device globals; no allocations allowed) ----
__device__ float  g_eNorm[KCODE];
__device__ float  g_znorm[N_TOK];
__device__ float  g_sumE[DDIM];
__device__ float  g_sumZ[DDIM];
__device__ int    g_counts[KCODE];
__device__ int    g_idx[N_TOK];
__device__ double g_loss_acc;
__device__ double g_zsq_acc;
__device__ double g_e2_acc;

__device__ __nv_bfloat16 g_Zb[(size_t)N_TOK * DDIM];    // 16MB token-major bf16
__device__ float         g_Zt[(size_t)N_TOK * DDIM];    // 32MB token-major fp32
__device__ __nv_bfloat16 g_Eb[(size_t)KCODE * DDIM];    // 512KB
__device__ int            g_candCnt[N_TOK];              // 128KB
__device__ unsigned short g_cand[(size_t)N_TOK * CAND_CAP]; // 2MB

// ------------------------------------------------------------------
__global__ void k_zero() {
    int t = blockIdx.x * 256 + threadIdx.x;
    if (t < KCODE) g_counts[t] = 0;
    if (t < DDIM)  { g_sumE[t] = 0.f; g_sumZ[t] = 0.f; }
    if (t == 0) { g_loss_acc = 0.0; g_zsq_acc = 0.0; g_e2_acc = 0.0; }
}

// one pass over E: per-code norm, bf16 convert, column sums, total e^2
__global__ void k_estats(const float* __restrict__ E) {
    int k = blockIdx.x;
    int t = threadIdx.x;                      // 64 threads, 4 floats each
    float4 v = ((const float4*)(E + (size_t)k * DDIM))[t];

    union { uint2 u; __nv_bfloat162 h2[2]; } pk;
    pk.h2[0] = __floats2bfloat162_rn(v.x, v.y);
    pk.h2[1] = __floats2bfloat162_rn(v.z, v.w);
    *(uint2*)&g_Eb[(size_t)k * DDIM + t * 4] = pk.u;

    atomicAdd(&g_sumE[t * 4 + 0], v.x);
    atomicAdd(&g_sumE[t * 4 + 1], v.y);
    atomicAdd(&g_sumE[t * 4 + 2], v.z);
    atomicAdd(&g_sumE[t * 4 + 3], v.w);

    float s = v.x * v.x + v.y * v.y + v.z * v.z + v.w * v.w;
    #pragma unroll
    for (int o = 16; o; o >>= 1) s += __shfl_down_sync(0xffffffffu, s, o);
    __shared__ float ws[2];
    if ((t & 31) == 0) ws[t >> 5] = s;
    __syncthreads();
    if (t == 0) {
        float tot = ws[0] + ws[1];
        g_eNorm[k] = tot;
        atomicAdd(&g_e2_acc, (double)tot);
    }
}

// ------------------------------------------------------------------
// ONE pass over Z: transpose -> Zt (fp32) + Zb (bf16), per-token znorm,
// per-d column sums (g_sumZ), and total z^2 (double) — replaces k_sumz.
__global__ __launch_bounds__(256) void k_prep(const float* __restrict__ Z) {
    __shared__ float tile[256][33];
    __shared__ float znpart[8][32];
    int tid = threadIdx.x;
    int b   = blockIdx.x >> 5;
    int hw0 = (blockIdx.x & 31) << 5;
    int lane = tid & 31, dg = tid >> 5;     // dg 0..7
    #pragma unroll
    for (int i = 0; i < 32; i++) {
        int d = dg * 32 + i;
        tile[d][lane] = Z[(((size_t)b * DDIM + d) << 10) + hw0 + lane];
    }
    __syncthreads();
    int h = tid & 31, ds = tid >> 5;        // ds 0..7 (d segment of 32)
    size_t tk = (size_t)b * 1024 + hw0 + h;
    float buf[32];
    float zp = 0.f;
    #pragma unroll
    for (int i = 0; i < 32; i++) {
        buf[i] = tile[ds * 32 + i][h];
        zp += buf[i] * buf[i];
    }
    znpart[ds][h] = zp;
    #pragma unroll
    for (int q = 0; q < 8; q++)
        *(float4*)&g_Zt[tk * DDIM + ds * 32 + q * 4] =
            make_float4(buf[q*4], buf[q*4+1], buf[q*4+2], buf[q*4+3]);
    #pragma unroll
    for (int q = 0; q < 4; q++) {
        union { uint4 u; __nv_bfloat162 h2[4]; } pk;
        #pragma unroll
        for (int j = 0; j < 4; j++)
            pk.h2[j] = __floats2bfloat162_rn(buf[q*8 + j*2], buf[q*8 + j*2 + 1]);
        *(uint4*)&g_Zb[tk * DDIM + ds * 32 + q * 8] = pk.u;
    }

    // per-d sums over this block's 32 tokens: butterfly per i, lane i keeps d=ds*32+i
    float zdsum = 0.f;
    #pragma unroll
    for (int i = 0; i < 32; i++) {
        float s = buf[i];
        #pragma unroll
        for (int o = 16; o; o >>= 1) s += __shfl_xor_sync(0xffffffffu, s, o);
        if (h == i) zdsum = s;
    }
    atomicAdd(&g_sumZ[ds * 32 + h], zdsum);   // spread addresses across lanes

    __syncthreads();
    if (tid < 32) {
        float s = znpart[0][tid];
        #pragma unroll
        for (int dd = 1; dd < 8; dd++) s += znpart[dd][tid];
        g_znorm[(size_t)b * 1024 + hw0 + tid] = s;
        float w = s;
        #pragma unroll
        for (int o = 16; o; o >>= 1) w += __shfl_xor_sync(0xffffffffu, w, o);
        if (tid == 0) atomicAdd(&g_zsq_acc, (double)w);
    }
}

// ------------------------------------------------------------------
__device__ __forceinline__ void mma_bf16(float* c, const uint32_t* a, const uint32_t* b) {
    asm volatile(
        "mma.sync.aligned.m16n8k16.row.col.f32.bf16.bf16.f32 "
        "{%0,%1,%2,%3}, {%4,%5,%6,%7}, {%8,%9}, {%0,%1,%2,%3};\n"
        : "+f"(c[0]), "+f"(c[1]), "+f"(c[2]), "+f"(c[3])
        : "r"(a[0]), "r"(a[1]), "r"(a[2]), "r"(a[3]), "r"(b[0]), "r"(b[1]));
}

// bf16-MMA + margin-candidate capture. CTA = 256 tokens x full K (16 chunks of 64).
// Candidates dumped to global; exact rescore happens in k_rescore (keeps this
// kernel's register count low so the MMA mainloop never spills).
#define SM_AS   0
#define SM_BS   33792
#define SM_RMIN (33792 + 8448)
#define SM_CMIN (SM_RMIN + 256)
#define SM_CNT  (SM_CMIN + 512)
#define SM_CAND (SM_CNT + 256)
#define SMEM_MMA_BYTES ((SM_CAND + 4096) * 4)

__global__ __launch_bounds__(512) void k_mma() {
    extern __shared__ uint32_t sm[];
    uint32_t* As = sm + SM_AS;           // [256][132]
    uint32_t* Bs = sm + SM_BS;           // [64][132]
    float*  runmin = (float*)(sm + SM_RMIN);
    float*  chmin  = (float*)(sm + SM_CMIN);   // [256][2]
    int*    cnt    = (int*)(sm + SM_CNT);
    unsigned short* cand = (unsigned short*)(sm + SM_CAND); // [256][32]

    int tid = threadIdx.x;
    int tb  = blockIdx.x;                // 0..127, 256 tokens each

    if (tid < 256) { runmin[tid] = 3.4e38f; cnt[tid] = 0; }

    #pragma unroll
    for (int i = 0; i < 16; i++) {
        int c = tid + 512 * i;
        int row = c >> 5, col = c & 31;
        uint4 v = *(const uint4*)(g_Zb + ((size_t)(tb * 256 + row)) * DDIM + col * 8);
        *(uint4*)(As + row * 132 + col * 4) = v;
    }

    int w = tid >> 5, l = tid & 31;
    int m0 = (w & 7) * 32, n0 = (w >> 3) * 32;
    int ng = w >> 3;
    int l4 = l >> 2, lm = l & 3;

    float acc[2][4][4];
    #pragma unroll
    for (int mf = 0; mf < 2; mf++)
        #pragma unroll
        for (int nf = 0; nf < 4; nf++)
            #pragma unroll
            for (int q = 0; q < 4; q++) acc[mf][nf][q] = 0.f;

    for (int ch = 0; ch < 16; ch++) {
        __syncthreads();
        #pragma unroll
        for (int i = 0; i < 4; i++) {
            int c = tid + 512 * i;
            int row = c >> 5, col = c & 31;
            uint4 v = *(const uint4*)(g_Eb + ((size_t)(ch * 64 + row)) * DDIM + col * 8);
            *(uint4*)(Bs + row * 132 + col * 4) = v;
        }
        __syncthreads();

        #pragma unroll
        for (int ks = 0; ks < 16; ks++) {
            int ka = ks * 8 + lm;
            uint32_t a[2][4], b[4][2];
            #pragma unroll
            for (int mf = 0; mf < 2; mf++) {
                int r = m0 + mf * 16 + l4;
                a[mf][0] = As[r * 132 + ka];
                a[mf][1] = As[(r + 8) * 132 + ka];
                a[mf][2] = As[r * 132 + ka + 4];
                a[mf][3] = As[(r + 8) * 132 + ka + 4];
            }
            #pragma unroll
            for (int nf = 0; nf < 4; nf++) {
                int n = n0 + nf * 8 + l4;
                b[nf][0] = Bs[n * 132 + ka];
                b[nf][1] = Bs[n * 132 + ka + 4];
            }
            #pragma unroll
            for (int mf = 0; mf < 2; mf++)
                #pragma unroll
                for (int nf = 0; nf < 4; nf++)
                    mma_bf16(acc[mf][nf], a[mf], b[nf]);
        }

        // --- epilogue: s = en - 2*dot, chunk-min, margin candidates ---
        float rmin[2][2];
        #pragma unroll
        for (int mf = 0; mf < 2; mf++) {
            rmin[mf][0] = 3.4e38f; rmin[mf][1] = 3.4e38f;
            #pragma unroll
            for (int nf = 0; nf < 4; nf++) {
                int cg = ch * 64 + n0 + nf * 8 + lm * 2;
                float2 en = *(const float2*)&g_eNorm[cg];
                acc[mf][nf][0] = en.x - 2.f * acc[mf][nf][0];
                acc[mf][nf][1] = en.y - 2.f * acc[mf][nf][1];
                acc[mf][nf][2] = en.x - 2.f * acc[mf][nf][2];
                acc[mf][nf][3] = en.y - 2.f * acc[mf][nf][3];
                rmin[mf][0] = fminf(rmin[mf][0], fminf(acc[mf][nf][0], acc[mf][nf][1]));
                rmin[mf][1] = fminf(rmin[mf][1], fminf(acc[mf][nf][2], acc[mf][nf][3]));
            }
        }
        #pragma unroll
        for (int mf = 0; mf < 2; mf++)
            #pragma unroll
            for (int hf = 0; hf < 2; hf++) {
                float v = rmin[mf][hf];
                v = fminf(v, __shfl_xor_sync(0xffffffffu, v, 1));
                v = fminf(v, __shfl_xor_sync(0xffffffffu, v, 2));
                rmin[mf][hf] = v;
            }
        if (lm == 0) {
            #pragma unroll
            for (int mf = 0; mf < 2; mf++)
                #pragma unroll
                for (int hf = 0; hf < 2; hf++)
                    chmin[(m0 + mf * 16 + hf * 8 + l4) * 2 + ng] = rmin[mf][hf];
        }
        __syncthreads();
        if (tid < 256)
            runmin[tid] = fminf(runmin[tid], fminf(chmin[tid * 2], chmin[tid * 2 + 1]));
        __syncthreads();

        #pragma unroll
        for (int mf = 0; mf < 2; mf++) {
            int r0 = m0 + mf * 16 + l4;
            float t0 = runmin[r0] + MARGIN;
            float t1 = runmin[r0 + 8] + MARGIN;
            #pragma unroll
            for (int nf = 0; nf < 4; nf++) {
                int cg = ch * 64 + n0 + nf * 8 + lm * 2;
                if (acc[mf][nf][0] <= t0) {
                    int p = atomicAdd(&cnt[r0], 1);
                    if (p < CAND_CAP) cand[r0 * CAND_CAP + p] = (unsigned short)cg;
                }
                if (acc[mf][nf][1] <= t0) {
                    int p = atomicAdd(&cnt[r0], 1);
                    if (p < CAND_CAP) cand[r0 * CAND_CAP + p] = (unsigned short)(cg + 1);
                }
                if (acc[mf][nf][2] <= t1) {
                    int p = atomicAdd(&cnt[r0 + 8], 1);
                    if (p < CAND_CAP) cand[(r0 + 8) * CAND_CAP + p] = (unsigned short)cg;
                }
                if (acc[mf][nf][3] <= t1) {
                    int p = atomicAdd(&cnt[r0 + 8], 1);
                    if (p < CAND_CAP) cand[(r0 + 8) * CAND_CAP + p] = (unsigned short)(cg + 1);
                }
                acc[mf][nf][0] = 0.f; acc[mf][nf][1] = 0.f;
                acc[mf][nf][2] = 0.f; acc[mf][nf][3] = 0.f;
            }
        }
    }
    __syncthreads();

    // dump counts + candidate lists to global
    if (tid < 256) g_candCnt[tb * 256 + tid] = cnt[tid];
    {
        int row = tid >> 1, half = tid & 1;         // 512 threads: 2 per row
        const uint4* src = (const uint4*)(cand + row * CAND_CAP) + half * 2;
        uint4* dst = (uint4*)(g_cand + ((size_t)(tb * 256 + row)) * CAND_CAP) + half * 2;
        dst[0] = src[0];
        dst[1] = src[1];
    }
}

// ------------------------------------------------------------------
// exact fp32 rescore of candidate lists: warp per token, reference rounding
// emulation + explicit lowest-index tie-break (lists are unordered).
__global__ __launch_bounds__(256) void k_rescore(const float* __restrict__ E) {
    int t = blockIdx.x * 8 + (threadIdx.x >> 5);
    int l = threadIdx.x & 31;

    float zr[8];
    *(float4*)&zr[0] = *(const float4*)&g_Zt[(size_t)t * DDIM + l * 8];
    *(float4*)&zr[4] = *(const float4*)&g_Zt[(size_t)t * DDIM + l * 8 + 4];
    float szn = g_znorm[t];
    int c = g_candCnt[t];

    float best = 3.4e38f;
    int   bidx = 0;
    if (c <= CAND_CAP) {
        for (int j = 0; j < c; j++) {
            int code = g_cand[(size_t)t * CAND_CAP + j];
            const float* e = E + (size_t)code * DDIM + l * 8;
            float4 e0 = *(const float4*)e;
            float4 e1 = *(const float4*)(e + 4);
            float p = zr[0] * e0.x;
            p = fmaf(zr[1], e0.y, p);
            p = fmaf(zr[2], e0.z, p);
            p = fmaf(zr[3], e0.w, p);
            p = fmaf(zr[4], e1.x, p);
            p = fmaf(zr[5], e1.y, p);
            p = fmaf(zr[6], e1.z, p);
            p = fmaf(zr[7], e1.w, p);
            #pragma unroll
            for (int o = 16; o; o >>= 1) p += __shfl_xor_sync(0xffffffffu, p, o);
            float t1 = __fadd_rn(szn, g_eNorm[code]);
            float s  = __fadd_rn(t1, -2.0f * p);
            if (s < best || (s == best && code < bidx)) { best = s; bidx = code; }
        }
    } else {
        for (int code = 0; code < KCODE; code++) {
            const float* e = E + (size_t)code * DDIM + l * 8;
            float4 e0 = *(const float4*)e;
            float4 e1 = *(const float4*)(e + 4);
            float p = zr[0] * e0.x;
            p = fmaf(zr[1], e0.y, p);
            p = fmaf(zr[2], e0.z, p);
            p = fmaf(zr[3], e0.w, p);
            p = fmaf(zr[4], e1.x, p);
            p = fmaf(zr[5], e1.y, p);
            p = fmaf(zr[6], e1.z, p);
            p = fmaf(zr[7], e1.w, p);
            #pragma unroll
            for (int o = 16; o; o >>= 1) p += __shfl_xor_sync(0xffffffffu, p, o);
            float t1 = __fadd_rn(szn, g_eNorm[code]);
            float s  = __fadd_rn(t1, -2.0f * p);
            if (s < best) { best = s; bidx = code; }
        }
    }
    if (l == 0) {
        g_idx[t] = bidx;
        atomicAdd(&g_counts[bidx], 1);
    }
}

// ------------------------------------------------------------------
// gather codes -> out (NCHW), accumulate loss sum
__global__ __launch_bounds__(256) void k_out(const float* __restrict__ Z,
                                             const float* __restrict__ E,
                                             float* __restrict__ out) {
    __shared__ int sidx[128];
    int tid = threadIdx.x;
    int tb  = blockIdx.x;
    int b   = tb >> 3;
    int hw0 = (tb & 7) << 7;
    if (tid < 128) sidx[tid] = g_idx[tb * 128 + tid];
    __syncthreads();

    int t  = tid & 127;
    int dg = tid >> 7;
    int myidx = sidx[t];
    size_t zb = ((size_t)b * DDIM) * HW_ + hw0 + t;

    double lsum = 0.0;
    for (int d = dg; d < DDIM; d += 2) {
        float ov = E[(size_t)myidx * DDIM + d];
        float zv = Z[zb + (size_t)d * HW_];
        out[zb + (size_t)d * HW_] = ov;
        float df = ov - zv;
        lsum += (double)df * (double)df;
    }

    __shared__ double sred[256];
    sred[tid] = lsum;
    __syncthreads();
    for (int o = 128; o; o >>= 1) {
        if (tid < o) sred[tid] += sred[tid + o];
        __syncthreads();
    }
    if (tid == 0) atomicAdd(&g_loss_acc, sred[0]);
}

// ------------------------------------------------------------------
__global__ void k_final(float* __restrict__ tail) {
    __shared__ double shd[256];
    __shared__ double she[256];
    int tid = threadIdx.x;

    double dot = (tid < DDIM) ? (double)g_sumZ[tid] * (double)g_sumE[tid] : 0.0;
    double ent = 0.0;
    for (int k = tid; k < KCODE; k += 256) {
        double p = (double)g_counts[k] / (double)N_TOK;
        ent += p * log(p + 1e-10);
    }
    shd[tid] = dot; she[tid] = ent;
    __syncthreads();
    for (int o = 128; o; o >>= 1) {
        if (tid < o) { shd[tid] += shd[tid + o]; she[tid] += she[tid + o]; }
        __syncthreads();
    }
    if (tid == 0) {
        double md = g_zsq_acc / (double)N_TOK
                  + g_e2_acc  / (double)KCODE
                  - 2.0 * shd[0] / ((double)N_TOK * (double)KCODE);
        double loss = 1.25 * g_loss_acc / ((double)N_TOK * (double)DDIM);
        double perp = exp(-she[0]);
        tail[0] = (float)loss;
        tail[1] = (float)perp;
        tail[2] = (float)md;
    }
}

// ------------------------------------------------------------------
extern "C" void kernel_launch(void* const* d_in, const int* in_sizes, int n_in,
                              void* d_out, int out_size) {
    const float* Z = (const float*)d_in[0];   // [32,256,32,32]
    const float* E = (const float*)d_in[1];   // [1024,256]
    float* out = (float*)d_out;

    cudaFuncSetAttribute(k_mma, cudaFuncAttributeMaxDynamicSharedMemorySize,
                         SMEM_MMA_BYTES);

    k_zero   <<<4, 256>>>();
    k_estats <<<KCODE, 64>>>(E);
    k_prep   <<<1024, 256>>>(Z);
    k_mma    <<<128, 512, SMEM_MMA_BYTES>>>();
    k_rescore<<<4096, 256>>>(E);
    k_out    <<<256, 256>>>(Z, E, out);
    k_final  <<<1, 256>>>(out + (out_size - 3));
}

// round 15
// speedup vs baseline: 1.9286x; 1.0561x over previous
// R15: resubmit of the R9 LDSM build — two infra failures (R10 node bring-up,
// R14 container) mean the ldmatrix theory is still unmeasured. No logic changes.
#include <cuda_runtime.h>
#include <cuda_bf16.h>
#include <math.h>
#include <stdint.h>

#define N_TOK  32768
#define DDIM   256
#define KCODE  1024
#define HW_    1024
#define BATCH  32
#define MARGIN 2.0e-3f
#define CAND_CAP 32

// ---- scratch (static device globals; no allocations allowed) ----
__device__ float  g_eNorm[KCODE];
__device__ float  g_znorm[N_TOK];
__device__ float  g_sumE[DDIM];
__device__ float  g_sumZ[DDIM];
__device__ int    g_counts[KCODE];
__device__ int    g_idx[N_TOK];
__device__ double g_loss_acc;
__device__ double g_zsq_acc;
__device__ double g_e2_acc;

__device__ __nv_bfloat16 g_Zb[(size_t)N_TOK * DDIM];    // 16MB token-major bf16
__device__ float         g_Zt[(size_t)N_TOK * DDIM];    // 32MB token-major fp32
__device__ __nv_bfloat16 g_Eb[(size_t)KCODE * DDIM];    // 512KB
__device__ int            g_candCnt[N_TOK];              // 128KB
__device__ unsigned short g_cand[(size_t)N_TOK * CAND_CAP]; // 2MB

// ------------------------------------------------------------------
__global__ void k_zero() {
    int t = blockIdx.x * 256 + threadIdx.x;
    if (t < KCODE) g_counts[t] = 0;
    if (t < DDIM)  { g_sumE[t] = 0.f; g_sumZ[t] = 0.f; }
    if (t == 0) { g_loss_acc = 0.0; g_zsq_acc = 0.0; g_e2_acc = 0.0; }
}

// one pass over E: per-code norm, bf16 convert, column sums, total e^2
__global__ void k_estats(const float* __restrict__ E) {
    int k = blockIdx.x;
    int t = threadIdx.x;                      // 64 threads, 4 floats each
    float4 v = ((const float4*)(E + (size_t)k * DDIM))[t];

    union { uint2 u; __nv_bfloat162 h2[2]; } pk;
    pk.h2[0] = __floats2bfloat162_rn(v.x, v.y);
    pk.h2[1] = __floats2bfloat162_rn(v.z, v.w);
    *(uint2*)&g_Eb[(size_t)k * DDIM + t * 4] = pk.u;

    atomicAdd(&g_sumE[t * 4 + 0], v.x);
    atomicAdd(&g_sumE[t * 4 + 1], v.y);
    atomicAdd(&g_sumE[t * 4 + 2], v.z);
    atomicAdd(&g_sumE[t * 4 + 3], v.w);

    float s = v.x * v.x + v.y * v.y + v.z * v.z + v.w * v.w;
    #pragma unroll
    for (int o = 16; o; o >>= 1) s += __shfl_down_sync(0xffffffffu, s, o);
    __shared__ float ws[2];
    if ((t & 31) == 0) ws[t >> 5] = s;
    __syncthreads();
    if (t == 0) {
        float tot = ws[0] + ws[1];
        g_eNorm[k] = tot;
        atomicAdd(&g_e2_acc, (double)tot);
    }
}

// ------------------------------------------------------------------
// ONE pass over Z: transpose -> Zt (fp32) + Zb (bf16), per-token znorm,
// per-d column sums (g_sumZ), and total z^2 (double).
__global__ __launch_bounds__(256) void k_prep(const float* __restrict__ Z) {
    __shared__ float tile[256][33];
    __shared__ float znpart[8][32];
    int tid = threadIdx.x;
    int b   = blockIdx.x >> 5;
    int hw0 = (blockIdx.x & 31) << 5;
    int lane = tid & 31, dg = tid >> 5;     // dg 0..7
    #pragma unroll
    for (int i = 0; i < 32; i++) {
        int d = dg * 32 + i;
        tile[d][lane] = Z[(((size_t)b * DDIM + d) << 10) + hw0 + lane];
    }
    __syncthreads();
    int h = tid & 31, ds = tid >> 5;        // ds 0..7 (d segment of 32)
    size_t tk = (size_t)b * 1024 + hw0 + h;
    float buf[32];
    float zp = 0.f;
    #pragma unroll
    for (int i = 0; i < 32; i++) {
        buf[i] = tile[ds * 32 + i][h];
        zp += buf[i] * buf[i];
    }
    znpart[ds][h] = zp;
    #pragma unroll
    for (int q = 0; q < 8; q++)
        *(float4*)&g_Zt[tk * DDIM + ds * 32 + q * 4] =
            make_float4(buf[q*4], buf[q*4+1], buf[q*4+2], buf[q*4+3]);
    #pragma unroll
    for (int q = 0; q < 4; q++) {
        union { uint4 u; __nv_bfloat162 h2[4]; } pk;
        #pragma unroll
        for (int j = 0; j < 4; j++)
            pk.h2[j] = __floats2bfloat162_rn(buf[q*8 + j*2], buf[q*8 + j*2 + 1]);
        *(uint4*)&g_Zb[tk * DDIM + ds * 32 + q * 8] = pk.u;
    }

    float zdsum = 0.f;
    #pragma unroll
    for (int i = 0; i < 32; i++) {
        float s = buf[i];
        #pragma unroll
        for (int o = 16; o; o >>= 1) s += __shfl_xor_sync(0xffffffffu, s, o);
        if (h == i) zdsum = s;
    }
    atomicAdd(&g_sumZ[ds * 32 + h], zdsum);

    __syncthreads();
    if (tid < 32) {
        float s = znpart[0][tid];
        #pragma unroll
        for (int dd = 1; dd < 8; dd++) s += znpart[dd][tid];
        g_znorm[(size_t)b * 1024 + hw0 + tid] = s;
        float w = s;
        #pragma unroll
        for (int o = 16; o; o >>= 1) w += __shfl_xor_sync(0xffffffffu, w, o);
        if (tid == 0) atomicAdd(&g_zsq_acc, (double)w);
    }
}

// ------------------------------------------------------------------
__device__ __forceinline__ void mma_bf16(float* c, const uint32_t* a, const uint32_t* b) {
    asm volatile(
        "mma.sync.aligned.m16n8k16.row.col.f32.bf16.bf16.f32 "
        "{%0,%1,%2,%3}, {%4,%5,%6,%7}, {%8,%9}, {%0,%1,%2,%3};\n"
        : "+f"(c[0]), "+f"(c[1]), "+f"(c[2]), "+f"(c[3])
        : "r"(a[0]), "r"(a[1]), "r"(a[2]), "r"(a[3]), "r"(b[0]), "r"(b[1]));
}

__device__ __forceinline__ void ldsm_x4(uint32_t* r, uint32_t saddr) {
    asm volatile(
        "ldmatrix.sync.aligned.m8n8.x4.shared.b16 {%0,%1,%2,%3}, [%4];\n"
        : "=r"(r[0]), "=r"(r[1]), "=r"(r[2]), "=r"(r[3]) : "r"(saddr));
}

// bf16-MMA + margin-candidate capture. CTA = 256 tokens x full K (16 chunks of 64).
// Fragments loaded via ldmatrix (4 LDSM per 8 MMAs instead of 16 scalar LDS).
#define SM_AS   0
#define SM_BS   33792
#define SM_RMIN (33792 + 8448)
#define SM_CMIN (SM_RMIN + 256)
#define SM_CNT  (SM_CMIN + 512)
#define SM_CAND (SM_CNT + 256)
#define SMEM_MMA_BYTES ((SM_CAND + 4096) * 4)

__global__ __launch_bounds__(512) void k_mma() {
    extern __shared__ uint32_t sm[];
    uint32_t* As = sm + SM_AS;           // [256][132]
    uint32_t* Bs = sm + SM_BS;           // [64][132]
    float*  runmin = (float*)(sm + SM_RMIN);
    float*  chmin  = (float*)(sm + SM_CMIN);   // [256][2]
    int*    cnt    = (int*)(sm + SM_CNT);
    unsigned short* cand = (unsigned short*)(sm + SM_CAND); // [256][32]

    int tid = threadIdx.x;
    int tb  = blockIdx.x;                // 0..127, 256 tokens each

    if (tid < 256) { runmin[tid] = 3.4e38f; cnt[tid] = 0; }

    #pragma unroll
    for (int i = 0; i < 16; i++) {
        int c = tid + 512 * i;
        int row = c >> 5, col = c & 31;
        uint4 v = *(const uint4*)(g_Zb + ((size_t)(tb * 256 + row)) * DDIM + col * 8);
        *(uint4*)(As + row * 132 + col * 4) = v;
    }

    int w = tid >> 5, l = tid & 31;
    int m0 = (w & 7) * 32, n0 = (w >> 3) * 32;
    int ng = w >> 3;
    int l4 = l >> 2, lm = l & 3;

    // ldmatrix per-lane addresses (byte, shared space)
    uint32_t As_sh = (uint32_t)__cvta_generic_to_shared(As);
    uint32_t Bs_sh = (uint32_t)__cvta_generic_to_shared(Bs);
    int g8 = l >> 3, r8 = l & 7;
    // A tiles (reg order a0..a3): rows m+ (g&1)*8, k-halves by (g>>1)
    uint32_t aAddr[2], bAddr[2];
    #pragma unroll
    for (int mf = 0; mf < 2; mf++)
        aAddr[mf] = As_sh + (((m0 + mf * 16 + (g8 & 1) * 8 + r8) * 132) + (g8 >> 1) * 4) * 4;
    // B pair p covers nf=2p,2p+1: tiles (n rows by g>>1), k-halves by (g&1)
    #pragma unroll
    for (int p = 0; p < 2; p++)
        bAddr[p] = Bs_sh + (((n0 + p * 16 + (g8 >> 1) * 8 + r8) * 132) + (g8 & 1) * 4) * 4;

    float acc[2][4][4];
    #pragma unroll
    for (int mf = 0; mf < 2; mf++)
        #pragma unroll
        for (int nf = 0; nf < 4; nf++)
            #pragma unroll
            for (int q = 0; q < 4; q++) acc[mf][nf][q] = 0.f;

    for (int ch = 0; ch < 16; ch++) {
        __syncthreads();
        #pragma unroll
        for (int i = 0; i < 4; i++) {
            int c = tid + 512 * i;
            int row = c >> 5, col = c & 31;
            uint4 v = *(const uint4*)(g_Eb + ((size_t)(ch * 64 + row)) * DDIM + col * 8);
            *(uint4*)(Bs + row * 132 + col * 4) = v;
        }
        __syncthreads();

        #pragma unroll
        for (int ks = 0; ks < 16; ks++) {
            uint32_t a[2][4], b[2][4];
            ldsm_x4(a[0], aAddr[0] + ks * 32);
            ldsm_x4(a[1], aAddr[1] + ks * 32);
            ldsm_x4(b[0], bAddr[0] + ks * 32);
            ldsm_x4(b[1], bAddr[1] + ks * 32);
            #pragma unroll
            for (int mf = 0; mf < 2; mf++)
                #pragma unroll
                for (int nf = 0; nf < 4; nf++)
                    mma_bf16(acc[mf][nf], a[mf], &b[nf >> 1][(nf & 1) * 2]);
        }

        // --- epilogue: s = en - 2*dot, chunk-min, margin candidates ---
        float rmin[2][2];
        #pragma unroll
        for (int mf = 0; mf < 2; mf++) {
            rmin[mf][0] = 3.4e38f; rmin[mf][1] = 3.4e38f;
            #pragma unroll
            for (int nf = 0; nf < 4; nf++) {
                int cg = ch * 64 + n0 + nf * 8 + lm * 2;
                float2 en = *(const float2*)&g_eNorm[cg];
                acc[mf][nf][0] = en.x - 2.f * acc[mf][nf][0];
                acc[mf][nf][1] = en.y - 2.f * acc[mf][nf][1];
                acc[mf][nf][2] = en.x - 2.f * acc[mf][nf][2];
                acc[mf][nf][3] = en.y - 2.f * acc[mf][nf][3];
                rmin[mf][0] = fminf(rmin[mf][0], fminf(acc[mf][nf][0], acc[mf][nf][1]));
                rmin[mf][1] = fminf(rmin[mf][1], fminf(acc[mf][nf][2], acc[mf][nf][3]));
            }
        }
        #pragma unroll
        for (int mf = 0; mf < 2; mf++)
            #pragma unroll
            for (int hf = 0; hf < 2; hf++) {
                float v = rmin[mf][hf];
                v = fminf(v, __shfl_xor_sync(0xffffffffu, v, 1));
                v = fminf(v, __shfl_xor_sync(0xffffffffu, v, 2));
                rmin[mf][hf] = v;
            }
        if (lm == 0) {
            #pragma unroll
            for (int mf = 0; mf < 2; mf++)
                #pragma unroll
                for (int hf = 0; hf < 2; hf++)
                    chmin[(m0 + mf * 16 + hf * 8 + l4) * 2 + ng] = rmin[mf][hf];
        }
        __syncthreads();
        if (tid < 256)
            runmin[tid] = fminf(runmin[tid], fminf(chmin[tid * 2], chmin[tid * 2 + 1]));
        __syncthreads();

        #pragma unroll
        for (int mf = 0; mf < 2; mf++) {
            int r0 = m0 + mf * 16 + l4;
            float t0 = runmin[r0] + MARGIN;
            float t1 = runmin[r0 + 8] + MARGIN;
            #pragma unroll
            for (int nf = 0; nf < 4; nf++) {
                int cg = ch * 64 + n0 + nf * 8 + lm * 2;
                if (acc[mf][nf][0] <= t0) {
                    int p = atomicAdd(&cnt[r0], 1);
                    if (p < CAND_CAP) cand[r0 * CAND_CAP + p] = (unsigned short)cg;
                }
                if (acc[mf][nf][1] <= t0) {
                    int p = atomicAdd(&cnt[r0], 1);
                    if (p < CAND_CAP) cand[r0 * CAND_CAP + p] = (unsigned short)(cg + 1);
                }
                if (acc[mf][nf][2] <= t1) {
                    int p = atomicAdd(&cnt[r0 + 8], 1);
                    if (p < CAND_CAP) cand[(r0 + 8) * CAND_CAP + p] = (unsigned short)cg;
                }
                if (acc[mf][nf][3] <= t1) {
                    int p = atomicAdd(&cnt[r0 + 8], 1);
                    if (p < CAND_CAP) cand[(r0 + 8) * CAND_CAP + p] = (unsigned short)(cg + 1);
                }
                acc[mf][nf][0] = 0.f; acc[mf][nf][1] = 0.f;
                acc[mf][nf][2] = 0.f; acc[mf][nf][3] = 0.f;
            }
        }
    }
    __syncthreads();

    if (tid < 256) g_candCnt[tb * 256 + tid] = cnt[tid];
    {
        int row = tid >> 1, half = tid & 1;
        const uint4* src = (const uint4*)(cand + row * CAND_CAP) + half * 2;
        uint4* dst = (uint4*)(g_cand + ((size_t)(tb * 256 + row)) * CAND_CAP) + half * 2;
        dst[0] = src[0];
        dst[1] = src[1];
    }
}

// ------------------------------------------------------------------
// exact fp32 rescore + loss accumulation: warp per token.
// best = fl(fl(zn+en)-2*dot) equals the squared distance to the chosen code
// (1e-7 relative), so the loss sum is accumulated here and k_out needs no Z.
__global__ __launch_bounds__(256) void k_rescore(const float* __restrict__ E) {
    int t = blockIdx.x * 8 + (threadIdx.x >> 5);
    int l = threadIdx.x & 31;

    float zr[8];
    *(float4*)&zr[0] = *(const float4*)&g_Zt[(size_t)t * DDIM + l * 8];
    *(float4*)&zr[4] = *(const float4*)&g_Zt[(size_t)t * DDIM + l * 8 + 4];
    float szn = g_znorm[t];
    int c = g_candCnt[t];

    float best = 3.4e38f;
    int   bidx = 0;
    if (c <= CAND_CAP) {
        for (int j = 0; j < c; j++) {
            int code = g_cand[(size_t)t * CAND_CAP + j];
            const float* e = E + (size_t)code * DDIM + l * 8;
            float4 e0 = *(const float4*)e;
            float4 e1 = *(const float4*)(e + 4);
            float p = zr[0] * e0.x;
            p = fmaf(zr[1], e0.y, p);
            p = fmaf(zr[2], e0.z, p);
            p = fmaf(zr[3], e0.w, p);
            p = fmaf(zr[4], e1.x, p);
            p = fmaf(zr[5], e1.y, p);
            p = fmaf(zr[6], e1.z, p);
            p = fmaf(zr[7], e1.w, p);
            #pragma unroll
            for (int o = 16; o; o >>= 1) p += __shfl_xor_sync(0xffffffffu, p, o);
            float t1 = __fadd_rn(szn, g_eNorm[code]);
            float s  = __fadd_rn(t1, -2.0f * p);
            if (s < best || (s == best && code < bidx)) { best = s; bidx = code; }
        }
    } else {
        for (int code = 0; code < KCODE; code++) {
            const float* e = E + (size_t)code * DDIM + l * 8;
            float4 e0 = *(const float4*)e;
            float4 e1 = *(const float4*)(e + 4);
            float p = zr[0] * e0.x;
            p = fmaf(zr[1], e0.y, p);
            p = fmaf(zr[2], e0.z, p);
            p = fmaf(zr[3], e0.w, p);
            p = fmaf(zr[4], e1.x, p);
            p = fmaf(zr[5], e1.y, p);
            p = fmaf(zr[6], e1.z, p);
            p = fmaf(zr[7], e1.w, p);
            #pragma unroll
            for (int o = 16; o; o >>= 1) p += __shfl_xor_sync(0xffffffffu, p, o);
            float t1 = __fadd_rn(szn, g_eNorm[code]);
            float s  = __fadd_rn(t1, -2.0f * p);
            if (s < best) { best = s; bidx = code; }
        }
    }
    if (l == 0) {
        g_idx[t] = bidx;
        atomicAdd(&g_counts[bidx], 1);
    }

    // block loss reduce (8 warps)
    __shared__ double lsh[8];
    if (l == 0) lsh[threadIdx.x >> 5] = (double)best;
    __syncthreads();
    if (threadIdx.x == 0) {
        double s = lsh[0];
        #pragma unroll
        for (int i = 1; i < 8; i++) s += lsh[i];
        atomicAdd(&g_loss_acc, s);
    }
}

// ------------------------------------------------------------------
// pure gather: codes -> out (NCHW). No Z read (loss handled in k_rescore).
__global__ __launch_bounds__(256) void k_out(const float* __restrict__ E,
                                             float* __restrict__ out) {
    __shared__ int sidx[128];
    int tid = threadIdx.x;
    int tb  = blockIdx.x;
    int b   = tb >> 3;
    int hw0 = (tb & 7) << 7;
    if (tid < 128) sidx[tid] = g_idx[tb * 128 + tid];
    __syncthreads();

    int t  = tid & 127;
    int dg = tid >> 7;
    int myidx = sidx[t];
    size_t zb = ((size_t)b * DDIM) * HW_ + hw0 + t;

    #pragma unroll 4
    for (int d = dg; d < DDIM; d += 2)
        out[zb + (size_t)d * HW_] = E[(size_t)myidx * DDIM + d];
}

// ------------------------------------------------------------------
__global__ void k_final(float* __restrict__ tail) {
    __shared__ double shd[256];
    __shared__ double she[256];
    int tid = threadIdx.x;

    double dot = (tid < DDIM) ? (double)g_sumZ[tid] * (double)g_sumE[tid] : 0.0;
    double ent = 0.0;
    for (int k = tid; k < KCODE; k += 256) {
        double p = (double)g_counts[k] / (double)N_TOK;
        ent += p * log(p + 1e-10);
    }
    shd[tid] = dot; she[tid] = ent;
    __syncthreads();
    for (int o = 128; o; o >>= 1) {
        if (tid < o) { shd[tid] += shd[tid + o]; she[tid] += she[tid + o]; }
        __syncthreads();
    }
    if (tid == 0) {
        double md = g_zsq_acc / (double)N_TOK
                  + g_e2_acc  / (double)KCODE
                  - 2.0 * shd[0] / ((double)N_TOK * (double)KCODE);
        double loss = 1.25 * g_loss_acc / ((double)N_TOK * (double)DDIM);
        double perp = exp(-she[0]);
        tail[0] = (float)loss;
        tail[1] = (float)perp;
        tail[2] = (float)md;
    }
}

// ------------------------------------------------------------------
extern "C" void kernel_launch(void* const* d_in, const int* in_sizes, int n_in,
                              void* d_out, int out_size) {
    const float* Z = (const float*)d_in[0];   // [32,256,32,32]
    const float* E = (const float*)d_in[1];   // [1024,256]
    float* out = (float*)d_out;

    (void)cudaFuncSetAttribute(k_mma, cudaFuncAttributeMaxDynamicSharedMemorySize,
                               SMEM_MMA_BYTES);

    k_zero   <<<4, 256>>>();
    k_estats <<<KCODE, 64>>>(E);
    k_prep   <<<1024, 256>>>(Z);
    k_mma    <<<128, 512, SMEM_MMA_BYTES>>>();
    k_rescore<<<4096, 256>>>(E);
    k_out    <<<256, 256>>>(E, out);
    k_final  <<<1, 256>>>(out + (out_size - 3));
}